// round 12
// baseline (speedup 1.0000x reference)
#include <cuda_runtime.h>

#define FFT_N  4096
#define NT     256
#define PAD(i) ((i) + ((i) >> 4))
#define SMEM_E (FFT_N + (FFT_N >> 4))   // 4352 float2 = 34816 B

// Permuted, pre-normalized D table: Dperm[p] = D[digitrev16(p)] / N
__device__ float2 d_Dperm[FFT_N];

__global__ void dperm_init(const float2* __restrict__ D) {
    int p = blockIdx.x * blockDim.x + threadIdx.x;
    if (p < FFT_N) {
        int rev = ((p & 15) << 8) | (p & 240) | (p >> 8);  // swap base-16 digits 0<->2
        float2 d = D[rev];
        const float invN = 1.0f / (float)FFT_N;
        d_Dperm[p] = make_float2(d.x * invN, d.y * invN);
    }
}

__device__ __forceinline__ float2 cadd(float2 a, float2 b) { return make_float2(a.x + b.x, a.y + b.y); }
__device__ __forceinline__ float2 csub(float2 a, float2 b) { return make_float2(a.x - b.x, a.y - b.y); }
__device__ __forceinline__ float2 cmul(float2 a, float2 b) {
    return make_float2(fmaf(a.x, b.x, -a.y * b.y), fmaf(a.x, b.y, a.y * b.x));
}
template <int DIR>
__device__ __forceinline__ float2 rotI(float2 z) {
    return (DIR < 0) ? make_float2(z.y, -z.x) : make_float2(-z.y, z.x);
}
template <int DIR>
__device__ __forceinline__ float2 cmulc(float2 z, float cr, float ci_fwd) {
    float ci = (DIR < 0) ? ci_fwd : -ci_fwd;
    return cmul(z, make_float2(cr, ci));
}

template <int DIR>
__device__ __forceinline__ void dft4(float2& a, float2& b, float2& c, float2& d) {
    float2 t0 = cadd(a, c), t1 = csub(a, c);
    float2 t2 = cadd(b, d), t3 = rotI<DIR>(csub(b, d));
    a = cadd(t0, t2);
    b = cadd(t1, t3);
    c = csub(t0, t2);
    d = csub(t1, t3);
}

// 16-point DFT/IDFT as 4x4. Natural input v[n]; bin k lands at v[OUT(k)].
#define OUT(q) ((((q) & 3) << 2) | ((q) >> 2))

template <int DIR>
__device__ __forceinline__ void dft16(float2 v[16]) {
    const float C1 = 0.92387953251128675613f;
    const float S1 = 0.38268343236508977173f;
    const float H  = 0.70710678118654752440f;
    dft4<DIR>(v[0], v[4], v[8],  v[12]);
    dft4<DIR>(v[1], v[5], v[9],  v[13]);
    dft4<DIR>(v[2], v[6], v[10], v[14]);
    dft4<DIR>(v[3], v[7], v[11], v[15]);
    v[5]  = cmulc<DIR>(v[5],  C1, -S1);
    v[6]  = cmulc<DIR>(v[6],  H,  -H );
    v[7]  = cmulc<DIR>(v[7],  S1, -C1);
    v[9]  = cmulc<DIR>(v[9],  H,  -H );
    v[10] = rotI<DIR>(v[10]);
    v[11] = cmulc<DIR>(v[11], -H, -H );
    v[13] = cmulc<DIR>(v[13], S1, -C1);
    v[14] = cmulc<DIR>(v[14], -H, -H );
    v[15] = cmulc<DIR>(v[15], -C1, S1);
    dft4<DIR>(v[0],  v[1],  v[2],  v[3]);
    dft4<DIR>(v[4],  v[5],  v[6],  v[7]);
    dft4<DIR>(v[8],  v[9],  v[10], v[11]);
    dft4<DIR>(v[12], v[13], v[14], v[15]);
}

// v[idx(r)] *= exp(i*theta*r), r=1..15. ATOUT: apply at OUT positions (post-butterfly,
// where bin r lives); else at natural positions (pre-butterfly).
template <bool ATOUT>
__device__ __forceinline__ void ladder(float2 v[16], float theta) {
    float sw, cw;
    __sincosf(theta, &sw, &cw);
    float2 w1 = make_float2(cw, sw);
    float2 w = w1;
    v[ATOUT ? OUT(1) : 1] = cmul(v[ATOUT ? OUT(1) : 1], w);
#pragma unroll
    for (int r = 2; r < 16; r++) {
        w = cmul(w, w1);
        int p = ATOUT ? OUT(r) : r;
        v[p] = cmul(v[p], w);
    }
}

extern __shared__ float2 sm[];

__global__ void __launch_bounds__(NT, 3)
afdf_ct_kernel(const float2* __restrict__ x, const float2* __restrict__ A,
               float2* __restrict__ out) {
    const int i = threadIdx.x;
    const int o = i & 15, b = i >> 4;
    const size_t base = (size_t)blockIdx.x * FFT_N;
    const float TH1 = -6.283185307179586f * (float)i / (float)FFT_N;   // W4096^i
    const float TH2 = -6.283185307179586f * (float)o / 256.0f;         // W256^o

    float2 v[16];

    // ---- fwd DIF stage 1 (span 4096): gmem load + A scale, butterfly, twiddle ----
#pragma unroll
    for (int r = 0; r < 16; r++) {
        int c = i + NT * r;
        float2 xv = x[base + c];
        float2 a = A[c];
        v[r] = make_float2(a.x * xv.x, a.y * xv.y);   // independent re/im scale
    }
    dft16<-1>(v);
    ladder<true>(v, TH1);        // bin k1 at v[OUT(k1)] *= W4096^{i*k1}
#pragma unroll
    for (int q = 0; q < 16; q++) sm[PAD(i + NT * q)] = v[OUT(q)];
    __syncthreads();

    // ---- fwd DIF stage 2 (span 256), in-place ----
#pragma unroll
    for (int s = 0; s < 16; s++) v[s] = sm[PAD(256 * b + o + 16 * s)];
    dft16<-1>(v);
    ladder<true>(v, TH2);        // bin k2 *= W256^{o*k2}
#pragma unroll
    for (int q = 0; q < 16; q++) sm[PAD(256 * b + o + 16 * q)] = v[OUT(q)];
    __syncthreads();

    // ---- fwd stage 3 (span 16) + Dperm + inv stage 3, contiguous, no ladders ----
    {
#pragma unroll
        for (int q = 0; q < 16; q++) v[q] = sm[PAD(16 * i + q)];
        dft16<-1>(v);
        // bin q at v[OUT(q)]; multiply by Dperm[16i+q] (elementwise re/im, incl. 1/N)
        float2 w[16];
        const float4* dp = reinterpret_cast<const float4*>(&d_Dperm[16 * i]);
#pragma unroll
        for (int h = 0; h < 8; h++) {
            float4 dd = dp[h];
            float2 e0 = v[OUT(2 * h)], e1 = v[OUT(2 * h + 1)];
            w[2 * h]     = make_float2(dd.x * e0.x, dd.y * e0.y);
            w[2 * h + 1] = make_float2(dd.z * e1.x, dd.w * e1.y);
        }
        dft16<1>(w);             // unnormalized IDFT16 over the same 16 bins
#pragma unroll
        for (int q = 0; q < 16; q++) sm[PAD(16 * i + q)] = w[OUT(q)];
    }
    __syncthreads();

    // ---- inv DIT stage 2 (span 256), conj twiddle BEFORE butterfly, in-place ----
#pragma unroll
    for (int s = 0; s < 16; s++) v[s] = sm[PAD(256 * b + o + 16 * s)];
    ladder<false>(v, -TH2);      // undo W256^{o*s}
    dft16<1>(v);
#pragma unroll
    for (int q = 0; q < 16; q++) sm[PAD(256 * b + o + 16 * q)] = v[OUT(q)];
    __syncthreads();

    // ---- inv DIT stage 1 (span 4096) -> gmem, coalesced ----
#pragma unroll
    for (int r = 0; r < 16; r++) v[r] = sm[PAD(i + NT * r)];
    ladder<false>(v, -TH1);      // undo W4096^{i*r}
    dft16<1>(v);
#pragma unroll
    for (int q = 0; q < 16; q++) out[base + i + NT * q] = v[OUT(q)];
}

extern "C" void kernel_launch(void* const* d_in, const int* in_sizes, int n_in,
                              void* d_out, int out_size) {
    const float2* x = (const float2*)d_in[0];
    const float2* A = (const float2*)d_in[1];
    const float2* D = (const float2*)d_in[2];
    float2* out = (float2*)d_out;

    int rows = in_sizes[0] / (FFT_N * 2);   // (B, C, 2) float32 -> B rows

    dperm_init<<<FFT_N / 256, 256>>>(D);

    const int smem_bytes = SMEM_E * sizeof(float2);  // 34816 B
    cudaFuncSetAttribute(afdf_ct_kernel, cudaFuncAttributeMaxDynamicSharedMemorySize, smem_bytes);
    afdf_ct_kernel<<<rows, NT, smem_bytes>>>(x, A, out);
}

// round 13
// speedup vs baseline: 1.2841x; 1.2841x over previous
#include <cuda_runtime.h>
#include <math.h>

#define FFT_N  4096
#define NT     256
#define PAD(i) ((i) + ((i) >> 4))
#define SMEM_E (FFT_N + (FFT_N >> 4))   // 4352 float2 = 34816 B

__device__ __forceinline__ float2 cadd(float2 a, float2 b) { return make_float2(a.x + b.x, a.y + b.y); }
__device__ __forceinline__ float2 csub(float2 a, float2 b) { return make_float2(a.x - b.x, a.y - b.y); }
__device__ __forceinline__ float2 cmul(float2 a, float2 b) {
    return make_float2(fmaf(a.x, b.x, -a.y * b.y), fmaf(a.x, b.y, a.y * b.x));
}
// multiply by -i (DIR=-1, forward) or +i (DIR=+1, inverse)
template <int DIR>
__device__ __forceinline__ float2 rotI(float2 z) {
    return (DIR < 0) ? make_float2(z.y, -z.x) : make_float2(-z.y, z.x);
}
template <int DIR>
__device__ __forceinline__ float2 cmulc(float2 z, float cr, float ci_fwd) {
    float ci = (DIR < 0) ? ci_fwd : -ci_fwd;
    return cmul(z, make_float2(cr, ci));
}

// z * (H, -H) forward / (H, H) inverse  [W16^2], 2 FADD + 2 FMUL
template <int DIR>
__device__ __forceinline__ float2 mulW2(float2 z) {
    const float H = 0.70710678118654752440f;
    return (DIR < 0) ? make_float2(H * (z.x + z.y), H * (z.y - z.x))
                     : make_float2(H * (z.x - z.y), H * (z.x + z.y));
}
// z * (-H, -H) forward / (-H, H) inverse  [W16^6], 2 FADD + 2 FMUL
template <int DIR>
__device__ __forceinline__ float2 mulW6(float2 z) {
    const float H = 0.70710678118654752440f;
    return (DIR < 0) ? make_float2(H * (z.y - z.x), -H * (z.x + z.y))
                     : make_float2(-H * (z.x + z.y), H * (z.x - z.y));
}

template <int DIR>
__device__ __forceinline__ void dft4(float2& a, float2& b, float2& c, float2& d) {
    float2 t0 = cadd(a, c), t1 = csub(a, c);
    float2 t2 = cadd(b, d), t3 = rotI<DIR>(csub(b, d));
    a = cadd(t0, t2);
    b = cadd(t1, t3);
    c = csub(t0, t2);
    d = csub(t1, t3);
}

// 16-point DFT as 4x4. Input natural order; X[k1 + 4*k2] lands at v[4*k1 + k2].
#define OUT(q) ((((q) & 3) << 2) | ((q) >> 2))

template <int DIR>
__device__ __forceinline__ void dft16(float2 v[16]) {
    const float C1 = 0.92387953251128675613f;
    const float S1 = 0.38268343236508977173f;
    dft4<DIR>(v[0], v[4], v[8],  v[12]);
    dft4<DIR>(v[1], v[5], v[9],  v[13]);
    dft4<DIR>(v[2], v[6], v[10], v[14]);
    dft4<DIR>(v[3], v[7], v[11], v[15]);
    v[5]  = cmulc<DIR>(v[5],  C1, -S1);   // W16^1
    v[6]  = mulW2<DIR>(v[6]);             // W16^2
    v[7]  = cmulc<DIR>(v[7],  S1, -C1);   // W16^3
    v[9]  = mulW2<DIR>(v[9]);             // W16^2
    v[10] = rotI<DIR>(v[10]);             // W16^4
    v[11] = mulW6<DIR>(v[11]);            // W16^6
    v[13] = cmulc<DIR>(v[13], S1, -C1);   // W16^3
    v[14] = mulW6<DIR>(v[14]);            // W16^6
    v[15] = cmulc<DIR>(v[15], -C1, S1);   // W16^9
    dft4<DIR>(v[0],  v[1],  v[2],  v[3]);
    dft4<DIR>(v[4],  v[5],  v[6],  v[7]);
    dft4<DIR>(v[8],  v[9],  v[10], v[11]);
    dft4<DIR>(v[12], v[13], v[14], v[15]);
}

// v[r] *= exp(i*theta*r), r = 1..15 — each twiddle via independent MUFU sincos
// (no serial cmul chain: shorter dependency depth, work moves to the idle MUFU pipe)
__device__ __forceinline__ void twiddle_ladder(float2 v[16], float theta) {
#pragma unroll
    for (int r = 1; r < 16; r++) {
        float s, c;
        __sincosf(theta * (float)r, &s, &c);
        v[r] = cmul(v[r], make_float2(c, s));
    }
}

// Middle Stockham radix-16 stage (S=16), in-place smem (round-2 proven layout).
template <int DIR>
__device__ __forceinline__ void mid_stage(float2* sm, int i) {
    float2 v[16];
#pragma unroll
    for (int r = 0; r < 16; r++) v[r] = sm[PAD(i + NT * r)];
    int k = i & 15;
    float theta = ((DIR < 0) ? -6.283185307179586f : 6.283185307179586f)
                  * (float)k / 256.0f;
    twiddle_ladder(v, theta);
    dft16<DIR>(v);
    __syncthreads();
    int j = ((i & ~15) << 4) + k;
#pragma unroll
    for (int q = 0; q < 16; q++) sm[PAD(j + q * 16)] = v[OUT(q)];
    __syncthreads();
}

extern __shared__ float2 sm[];

__global__ void __launch_bounds__(NT, 3)
afdf16m_kernel(const float2* __restrict__ x, const float2* __restrict__ A,
               const float2* __restrict__ D, float2* __restrict__ out) {
    const int i = threadIdx.x;
    const size_t base = (size_t)blockIdx.x * FFT_N;

    // ---- fwd stage 0 (S=1, twiddle-free) fused with gmem load + A scale ----
    {
        float2 v[16];
#pragma unroll
        for (int r = 0; r < 16; r++) {
            int c = i + NT * r;
            float2 xv = x[base + c];
            float2 a = A[c];
            v[r] = make_float2(a.x * xv.x, a.y * xv.y);  // independent re/im scale
        }
        dft16<-1>(v);
#pragma unroll
        for (int q = 0; q < 16; q++) sm[PAD(16 * i + q)] = v[OUT(q)];
    }
    __syncthreads();

    // ---- fwd stage 1 (S=16) ----
    mid_stage<-1>(sm, i);

    // ---- fwd stage 2 (S=256) + D-scale + inv stage 0, in registers ----
    {
        float2 u[16];
#pragma unroll
        for (int r = 0; r < 16; r++) u[r] = sm[PAD(i + NT * r)];
        twiddle_ladder(u, -6.283185307179586f * (float)i / (float)FFT_N);
        dft16<-1>(u);
        // u[OUT(q)] = F[i + 256*q]
        const float invN = 1.0f / (float)FFT_N;
        float2 g[16];
#pragma unroll
        for (int r = 0; r < 16; r++) {
            float2 fv = u[OUT(r)];
            float2 d = D[i + NT * r];
            g[r] = make_float2(d.x * fv.x * invN, d.y * fv.y * invN);
        }
        dft16<1>(g);   // inverse stage 0 over the stride-256 set we hold
        __syncthreads();
#pragma unroll
        for (int q = 0; q < 16; q++) sm[PAD(16 * i + q)] = g[OUT(q)];
    }
    __syncthreads();

    // ---- inv stage 1 (S=16) ----
    mid_stage<1>(sm, i);

    // ---- inv stage 2 (S=256) -> gmem, coalesced ----
    {
        float2 u[16];
#pragma unroll
        for (int r = 0; r < 16; r++) u[r] = sm[PAD(i + NT * r)];
        twiddle_ladder(u, 6.283185307179586f * (float)i / (float)FFT_N);
        dft16<1>(u);
#pragma unroll
        for (int q = 0; q < 16; q++) out[base + i + NT * q] = u[OUT(q)];
    }
}

extern "C" void kernel_launch(void* const* d_in, const int* in_sizes, int n_in,
                              void* d_out, int out_size) {
    const float2* x = (const float2*)d_in[0];
    const float2* A = (const float2*)d_in[1];
    const float2* D = (const float2*)d_in[2];
    float2* out = (float2*)d_out;

    int rows = in_sizes[0] / (FFT_N * 2);   // (B, C, 2) float32 -> B rows

    const int smem_bytes = SMEM_E * sizeof(float2);  // 34816 B
    cudaFuncSetAttribute(afdf16m_kernel, cudaFuncAttributeMaxDynamicSharedMemorySize, smem_bytes);
    afdf16m_kernel<<<rows, NT, smem_bytes>>>(x, A, D, out);
}